// round 8
// baseline (speedup 1.0000x reference)
#include <cuda_runtime.h>
#include <cuda_fp8.h>
#include <cstdint>

#define B_    4
#define C_    64
#define T_    80
#define S_    2304
#define N_    128
#define NT_   10
#define TOUT_ 71
#define F_    320
#define KC    64
#define NCHUNK 36                 // chunks per tile
#define NTILE  160                // M128 tiles
#define GRID_G 148
#define NLONG  136                // CTAs with 39 chunks; rest 38

// ---------------- device scratch -------------------------------------------
__device__ __align__(16) uint8_t g_wsq[N_*S_];          // ws fp8 e4m3 (scaled), [n][s]
__device__ float g_wsDesc[N_];                           // per-n descale 2^-e
__device__ float g_Rpart[NTILE*2*2*N_];                  // [tile][ord][fl][n]

// ---------------- helpers ---------------------------------------------------
__device__ __forceinline__ uint32_t smem_u32(const void* p) {
    uint32_t a;
    asm("{ .reg .u64 t; cvta.to.shared.u64 t, %1; cvt.u32.u64 %0, t; }" : "=r"(a) : "l"(p));
    return a;
}
__device__ __forceinline__ uint32_t pack_e4m3x4(float f0, float f1, float f2, float f3) {
    uint32_t r;
    asm("{ .reg .b16 lo, hi;"
        " cvt.rn.satfinite.e4m3x2.f32 lo, %2, %1;"
        " cvt.rn.satfinite.e4m3x2.f32 hi, %4, %3;"
        " mov.b32 %0, {lo, hi}; }"
        : "=r"(r) : "f"(f0), "f"(f1), "f"(f2), "f"(f3));
    return r;
}
__device__ __forceinline__ void cp16(uint32_t dst, const void* src) {
    asm volatile("cp.async.cg.shared.global [%0], [%1], 16;" :: "r"(dst), "l"(src) : "memory");
}
#define CP_COMMIT() asm volatile("cp.async.commit_group;" ::: "memory")
#define CP_WAIT1()  asm volatile("cp.async.wait_group 1;" ::: "memory")

__device__ __forceinline__ void mma_fp8(float* d, const uint32_t* a, const uint32_t* b) {
    asm volatile("mma.sync.aligned.m16n8k32.row.col.f32.e4m3.e4m3.f32 "
        "{%0,%1,%2,%3}, {%4,%5,%6,%7}, {%8,%9}, {%0,%1,%2,%3};"
        : "+f"(d[0]), "+f"(d[1]), "+f"(d[2]), "+f"(d[3])
        : "r"(a[0]), "r"(a[1]), "r"(a[2]), "r"(a[3]), "r"(b[0]), "r"(b[1]));
}

// fp8 tile: 64B rows, 16B blocks w=0..3, physical block = w ^ ((row>>1)&3).
__device__ __forceinline__ uint32_t tswz(int row, int w) {
    return (uint32_t)(row * 64 + (((w ^ ((row >> 1) & 3)) & 3) << 4));
}

// ---------------------------------------------------------------------------
// 1) prep: blocks 0..127 -> wsq row n (fp8, power-of-2 scaled); 128..159 zero Rpart
// ---------------------------------------------------------------------------
__global__ void prep_kernel(const float* __restrict__ wx, const float* __restrict__ wy,
                            const float* __restrict__ wsx, const float* __restrict__ wsy) {
    int blk = blockIdx.x, tid = threadIdx.x;
    if (blk < 128) {
        int n = blk;
        __shared__ float gx[64], gy[36], invz, scal;
        if (tid < 64) {
            float rx = fmaxf(wsx[n], 0.0f);
            float inv2sx = 1.0f / (2.0f * (0.1f + rx * rx));
            float xv = ((float)tid - 32.0f + 0.5f) / 64.0f;
            float d = xv - wx[n];
            gx[tid] = expf(-d * d * inv2sx);
        } else if (tid < 100) {
            int yp = tid - 64;
            float ry = fmaxf(wsy[n], 0.0f);
            float inv2sy = 1.0f / (2.0f * (0.1f + ry * ry));
            float yv = ((float)yp - 18.0f + 0.5f) / 36.0f;
            float d = yv - wy[n];
            gy[yp] = expf(-d * d * inv2sy);
        }
        __syncthreads();
        if (tid == 0) {
            float sgx = 0.0f, sgy = 0.0f, mgx = 0.0f, mgy = 0.0f;
            for (int i = 0; i < 64; i++) { sgx += gx[i]; mgx = fmaxf(mgx, gx[i]); }
            for (int i = 0; i < 36; i++) { sgy += gy[i]; mgy = fmaxf(mgy, gy[i]); }
            float iz = 1.0f / (0.1f + sgx * sgy);
            invz = iz;
            float maxv = mgx * mgy * iz;                 // exact row max of ws
            int e = (int)floorf(log2f(240.0f / maxv));   // scale row max to ~240
            if (e > 24) e = 24;
            if (e < -24) e = -24;
            scal = exp2f((float)e);
            g_wsDesc[n] = exp2f((float)(-e));
        }
        __syncthreads();
        float f = invz * scal;
        for (int s = tid; s < S_; s += 256) {
            float v = gy[s >> 6] * gx[s & 63] * f;
            g_wsq[(size_t)n * S_ + s] = __nv_fp8_e4m3(v).__x;
        }
    } else {
        int base = (blk - 128) * 2560;
        for (int q = tid; q < 2560; q += 256) g_Rpart[base + q] = 0.0f;
    }
}

// ---------------------------------------------------------------------------
// 2) GEMM: grid 148, static chunk ranges, fp8 m16n8k32.
// ---------------------------------------------------------------------------
#define SM_A0   0
#define SM_A1   8192
#define SM_B0   16384
#define SM_B1   24576
#define SM_T1   32768
#define T1_STRIDE 132
#define SMEM_SZ (32768 + 128*T1_STRIDE*4)   // 100352

extern "C" __global__ void __launch_bounds__(256, 1)
gemm_kernel(const float* __restrict__ x, const float* __restrict__ wc) {
    extern __shared__ __align__(16) char smem[];
    const uint32_t sb = smem_u32(smem);
    const int tid  = threadIdx.x;
    const int wid  = tid >> 5;
    const int lane = tid & 31;
    const int wm   = wid & 3;
    const int wn   = wid >> 2;
    const int lrow = lane >> 2;
    const int lq   = lane & 3;
    const int lr   = tid >> 1;      // A loader row
    const int lh   = tid & 1;       // A k-half (32 floats)
    const int lb   = tid & 127;     // B loader row
    const int hb   = tid >> 7;      // B k-half (32 bytes)

    const int bi = blockIdx.x;
    const int s  = (bi < NLONG) ? 39 * bi : 39 * NLONG + 38 * (bi - NLONG);
    const int e  = s + ((bi < NLONG) ? 39 : 38);

    const uint32_t abuf[2] = { sb + SM_A0, sb + SM_A1 };
    const uint32_t bbuf[2] = { sb + SM_B0, sb + SM_B1 };

    // B issue: fp8 direct cp.async (2 x 16B per thread)
    auto issueB = [&](int g, int p) {
        int m = g / NCHUNK;
        int k = g - m * NCHUNK;
        const uint8_t* bs = g_wsq + (size_t)lb * S_ + k * KC + hb * 32;
#pragma unroll
        for (int j = 0; j < 2; j++)
            cp16(bbuf[p] + tswz(lb, hb * 2 + j), bs + j * 16);
    };

    // A stage: LDG fp32 into regs (double-buffered), cvt->fp8, STS
    float4 fa[2][8];
    auto ldA = [&](int g, int sbf) {
        int m = g / NCHUNK;
        int k = g - m * NCHUNK;
        int gr = m * 128 + lr;
        int f  = gr >> 6;
        int c  = gr & 63;
        int bb = f / T_;
        int tt = f - bb * T_;
        const float4* as = (const float4*)(x + ((size_t)((bb * C_ + c) * T_ + tt)) * S_
                                             + k * KC + lh * 32);
#pragma unroll
        for (int q = 0; q < 8; q++) fa[sbf][q] = __ldg(as + q);
    };
    auto stsA = [&](int sbf, int p) {
        uint32_t u[8];
#pragma unroll
        for (int j = 0; j < 8; j++)
            u[j] = pack_e4m3x4(fa[sbf][j].x, fa[sbf][j].y, fa[sbf][j].z, fa[sbf][j].w);
        uint32_t d0 = abuf[p] + tswz(lr, lh * 2);
        uint32_t d1 = abuf[p] + tswz(lr, lh * 2 + 1);
        asm volatile("st.shared.v4.b32 [%0], {%1,%2,%3,%4};"
            :: "r"(d0), "r"(u[0]), "r"(u[1]), "r"(u[2]), "r"(u[3]) : "memory");
        asm volatile("st.shared.v4.b32 [%0], {%1,%2,%3,%4};"
            :: "r"(d1), "r"(u[4]), "r"(u[5]), "r"(u[6]), "r"(u[7]) : "memory");
    };

    float acc[2][8][4];
#pragma unroll
    for (int mt = 0; mt < 2; mt++)
#pragma unroll
        for (int j = 0; j < 8; j++)
#pragma unroll
            for (int q = 0; q < 4; q++) acc[mt][j][q] = 0.0f;

    issueB(s, 0);     CP_COMMIT();
    issueB(s + 1, 1); CP_COMMIT();
    ldA(s, 0);
    ldA(s + 1, 1);

    float* Tsm = (float*)(smem + SM_T1);

    for (int g = s; g < e; g++) {
        const int p = (g - s) & 1;
        stsA(p, p);
        CP_WAIT1();
        __syncthreads();
        if (g + 2 < e) ldA(g + 2, p);

        const uint32_t Ab = abuf[p], Bb = bbuf[p];
#pragma unroll
        for (int q = 0; q < 2; q++) {
            uint32_t afr[2][4];
#pragma unroll
            for (int mt = 0; mt < 2; mt++) {
                int r0 = wm * 32 + mt * 16 + lrow;
                asm volatile("ld.shared.b32 %0, [%1];" : "=r"(afr[mt][0])
                             : "r"(Ab + tswz(r0,     q * 2)     + lq * 4));
                asm volatile("ld.shared.b32 %0, [%1];" : "=r"(afr[mt][1])
                             : "r"(Ab + tswz(r0 + 8, q * 2)     + lq * 4));
                asm volatile("ld.shared.b32 %0, [%1];" : "=r"(afr[mt][2])
                             : "r"(Ab + tswz(r0,     q * 2 + 1) + lq * 4));
                asm volatile("ld.shared.b32 %0, [%1];" : "=r"(afr[mt][3])
                             : "r"(Ab + tswz(r0 + 8, q * 2 + 1) + lq * 4));
            }
            uint32_t bfr[8][2];
#pragma unroll
            for (int j = 0; j < 8; j++) {
                int n = wn * 64 + j * 8 + lrow;
                asm volatile("ld.shared.b32 %0, [%1];" : "=r"(bfr[j][0])
                             : "r"(Bb + tswz(n, q * 2)     + lq * 4));
                asm volatile("ld.shared.b32 %0, [%1];" : "=r"(bfr[j][1])
                             : "r"(Bb + tswz(n, q * 2 + 1) + lq * 4));
            }
#pragma unroll
            for (int mt = 0; mt < 2; mt++)
#pragma unroll
                for (int j = 0; j < 8; j++)
                    mma_fp8(acc[mt][j], afr[mt], bfr[j]);
        }
        __syncthreads();
        if (g + 2 < e) issueB(g + 2, p);
        CP_COMMIT();

        // ---- tile boundary or range end: flush partial R ----
        if ((g + 1 == e) || ((g + 1) % NCHUNK == 0)) {
            int m = g / NCHUNK;
            __syncthreads();
#pragma unroll
            for (int mt = 0; mt < 2; mt++) {
#pragma unroll
                for (int j = 0; j < 8; j++) {
                    int r0  = wm * 32 + mt * 16 + lrow;
                    int col = wn * 64 + j * 8 + lq * 2;
                    uint32_t a0 = sb + SM_T1 + (uint32_t)((r0 * T1_STRIDE + col) * 4);
                    uint32_t a1 = sb + SM_T1 + (uint32_t)(((r0 + 8) * T1_STRIDE + col) * 4);
                    asm volatile("st.shared.v2.f32 [%0], {%1,%2};"
                                 :: "r"(a0), "f"(acc[mt][j][0]), "f"(acc[mt][j][1]));
                    asm volatile("st.shared.v2.f32 [%0], {%1,%2};"
                                 :: "r"(a1), "f"(acc[mt][j][2]), "f"(acc[mt][j][3]));
                }
            }
            __syncthreads();
            {
                int fl = tid >> 7;
                int n  = tid & 127;
                float sum = 0.0f;
#pragma unroll 16
                for (int c2 = 0; c2 < 64; c2++)
                    sum += Tsm[(fl * 64 + c2) * T1_STRIDE + n] * __ldg(&wc[c2 * N_ + n]);
                sum *= g_wsDesc[n];                       // undo ws power-of-2 scale
                int ord = (s > m * NCHUNK) ? 1 : 0;
                g_Rpart[m * 512 + ord * 256 + fl * 128 + n] = sum;
            }
#pragma unroll
            for (int mt = 0; mt < 2; mt++)
#pragma unroll
                for (int j = 0; j < 8; j++)
#pragma unroll
                    for (int q = 0; q < 4; q++) acc[mt][j][q] = 0.0f;
        }
    }
}

// ---------------------------------------------------------------------------
// 3) temporal conv: one warp per (b, n) row
// ---------------------------------------------------------------------------
__global__ void conv_kernel(const float* __restrict__ wt, const float* __restrict__ wb,
                            float* __restrict__ out) {
    __shared__ float rr[8][80];
    __shared__ float wts[8][10];
    int wid = threadIdx.x >> 5, lane = threadIdx.x & 31;
    int row = blockIdx.x * 8 + wid;        // row = b*N + n
    int b = row >> 7, n = row & 127;
    if (lane < 10) wts[wid][lane] = wt[lane * N_ + n];
#pragma unroll
    for (int t0 = lane; t0 < T_; t0 += 32) {
        int f = b * T_ + t0;
        int m = f >> 1, fl = f & 1;
        rr[wid][t0] = g_Rpart[m * 512 + fl * 128 + n]
                    + g_Rpart[m * 512 + 256 + fl * 128 + n];
    }
    __syncwarp();
    float bias = wb[n];
    for (int t0 = lane; t0 < TOUT_; t0 += 32) {
        float sum = bias;
#pragma unroll
        for (int k = 0; k < NT_; k++) sum += rr[wid][t0 + k] * wts[wid][k];
        out[(size_t)row * TOUT_ + t0] = sum;
    }
}

// ---------------------------------------------------------------------------
extern "C" void kernel_launch(void* const* d_in, const int* in_sizes, int n_in,
                              void* d_out, int out_size) {
    (void)in_sizes; (void)n_in; (void)out_size;
    const float* x   = (const float*)d_in[0];
    const float* wc  = (const float*)d_in[2];
    const float* wx  = (const float*)d_in[3];
    const float* wy  = (const float*)d_in[4];
    const float* wsx = (const float*)d_in[5];
    const float* wsy = (const float*)d_in[6];
    const float* wt  = (const float*)d_in[7];
    const float* wb  = (const float*)d_in[8];
    float* out = (float*)d_out;

    cudaFuncSetAttribute(gemm_kernel, cudaFuncAttributeMaxDynamicSharedMemorySize, SMEM_SZ);

    prep_kernel<<<160, 256>>>(wx, wy, wsx, wsy);
    gemm_kernel<<<GRID_G, 256, SMEM_SZ>>>(x, wc);
    conv_kernel<<<(B_ * N_) / 8, 256>>>(wt, wb, out);
}

// round 9
// speedup vs baseline: 1.4076x; 1.4076x over previous
#include <cuda_runtime.h>
#include <cuda_fp8.h>
#include <cstdint>

#define B_    4
#define C_    64
#define T_    80
#define S_    2304
#define N_    128
#define NT_   10
#define TOUT_ 71
#define F_    320
#define KC    64
#define NCHUNK 36                 // chunks per tile
#define NTILE  160                // M128 tiles
#define GRID_G 148
#define NLONG  136                // CTAs with 39 chunks; rest 38

// ---------------- device scratch -------------------------------------------
__device__ __align__(16) uint8_t g_wsq[N_*S_];          // ws fp8 e4m3 (scaled), [n][s]
__device__ float g_wsDesc[N_];                           // per-n descale 2^-e
__device__ float g_Rpart[NTILE*2*2*N_];                  // [tile][ord][fl][n]

// ---------------- helpers ---------------------------------------------------
__device__ __forceinline__ uint32_t smem_u32(const void* p) {
    uint32_t a;
    asm("{ .reg .u64 t; cvta.to.shared.u64 t, %1; cvt.u32.u64 %0, t; }" : "=r"(a) : "l"(p));
    return a;
}
__device__ __forceinline__ uint32_t pack_e4m3x4(float f0, float f1, float f2, float f3) {
    uint32_t r;
    asm("{ .reg .b16 lo, hi;"
        " cvt.rn.satfinite.e4m3x2.f32 lo, %2, %1;"
        " cvt.rn.satfinite.e4m3x2.f32 hi, %4, %3;"
        " mov.b32 %0, {lo, hi}; }"
        : "=r"(r) : "f"(f0), "f"(f1), "f"(f2), "f"(f3));
    return r;
}
__device__ __forceinline__ void cp16(uint32_t dst, const void* src) {
    asm volatile("cp.async.cg.shared.global [%0], [%1], 16;" :: "r"(dst), "l"(src) : "memory");
}
#define CP_COMMIT() asm volatile("cp.async.commit_group;" ::: "memory")
#define CP_WAIT1()  asm volatile("cp.async.wait_group 1;" ::: "memory")

__device__ __forceinline__ void mma_fp8(float* d, const uint32_t* a, const uint32_t* b) {
    asm volatile("mma.sync.aligned.m16n8k32.row.col.f32.e4m3.e4m3.f32 "
        "{%0,%1,%2,%3}, {%4,%5,%6,%7}, {%8,%9}, {%0,%1,%2,%3};"
        : "+f"(d[0]), "+f"(d[1]), "+f"(d[2]), "+f"(d[3])
        : "r"(a[0]), "r"(a[1]), "r"(a[2]), "r"(a[3]), "r"(b[0]), "r"(b[1]));
}

// --- A tile: fp32, 128 rows x 256B, 16B granules u=0..15.
// phys position proven conflict-free for both cp.async stores and frag loads.
__device__ __forceinline__ uint32_t aoff(int r, int u) {
    uint32_t phys = (uint32_t)((u & 8) | ((u ^ ((r & 1) << 2) ^ (r & 2) ^ (u >> 3)) & 7));
    return (uint32_t)(r * 256) + phys * 16u;
}
// --- B tile: fp8, rows of 64B, 16B blocks w=0..3 (R8-proven)
__device__ __forceinline__ uint32_t tswz(int row, int w) {
    return (uint32_t)(row * 64 + (((w ^ ((row >> 1) & 3)) & 3) << 4));
}

// ---------------------------------------------------------------------------
// 1) prep: blocks 0..127 -> wsq row n (fp8, power-of-2 scaled); 128..159 zero Rpart
// ---------------------------------------------------------------------------
__global__ void prep_kernel(const float* __restrict__ wx, const float* __restrict__ wy,
                            const float* __restrict__ wsx, const float* __restrict__ wsy) {
    int blk = blockIdx.x, tid = threadIdx.x;
    if (blk < 128) {
        int n = blk;
        __shared__ float gx[64], gy[36], invz, scal;
        if (tid < 64) {
            float rx = fmaxf(wsx[n], 0.0f);
            float inv2sx = 1.0f / (2.0f * (0.1f + rx * rx));
            float xv = ((float)tid - 32.0f + 0.5f) / 64.0f;
            float d = xv - wx[n];
            gx[tid] = expf(-d * d * inv2sx);
        } else if (tid < 100) {
            int yp = tid - 64;
            float ry = fmaxf(wsy[n], 0.0f);
            float inv2sy = 1.0f / (2.0f * (0.1f + ry * ry));
            float yv = ((float)yp - 18.0f + 0.5f) / 36.0f;
            float d = yv - wy[n];
            gy[yp] = expf(-d * d * inv2sy);
        }
        __syncthreads();
        if (tid == 0) {
            float sgx = 0.0f, sgy = 0.0f, mgx = 0.0f, mgy = 0.0f;
            for (int i = 0; i < 64; i++) { sgx += gx[i]; mgx = fmaxf(mgx, gx[i]); }
            for (int i = 0; i < 36; i++) { sgy += gy[i]; mgy = fmaxf(mgy, gy[i]); }
            float iz = 1.0f / (0.1f + sgx * sgy);
            invz = iz;
            float maxv = mgx * mgy * iz;
            int e = (int)floorf(log2f(240.0f / maxv));
            if (e > 24) e = 24;
            if (e < -24) e = -24;
            scal = exp2f((float)e);
            g_wsDesc[n] = exp2f((float)(-e));
        }
        __syncthreads();
        float f = invz * scal;
        for (int s = tid; s < S_; s += 256) {
            float v = gy[s >> 6] * gx[s & 63] * f;
            g_wsq[(size_t)n * S_ + s] = __nv_fp8_e4m3(v).__x;
        }
    } else {
        int base = (blk - 128) * 2560;
        for (int q = tid; q < 2560; q += 256) g_Rpart[base + q] = 0.0f;
    }
}

// ---------------------------------------------------------------------------
// 2) GEMM: grid 148, static chunk ranges. A fp32 cp.async, fp8 m16n8k32.
// ---------------------------------------------------------------------------
#define SM_A0   0
#define SM_A1   32768
#define SM_B0   65536
#define SM_B1   73728
#define SM_T1   81920
#define T1_STRIDE 132
#define SMEM_SZ (81920 + 128*T1_STRIDE*4)   // 149504

extern "C" __global__ void __launch_bounds__(256, 1)
gemm_kernel(const float* __restrict__ x, const float* __restrict__ wc) {
    extern __shared__ __align__(16) char smem[];
    const uint32_t sb = smem_u32(smem);
    const int tid  = threadIdx.x;
    const int wid  = tid >> 5;
    const int lane = tid & 31;
    const int wm   = wid & 3;
    const int wn   = wid >> 2;
    const int lrow = lane >> 2;
    const int lq   = lane & 3;
    const int lr   = tid >> 1;      // A loader row
    const int lh   = tid & 1;       // A loader half-row (8 granules)
    const int lb   = tid & 127;     // B loader row
    const int hb   = tid >> 7;      // B loader k-half

    const int bi = blockIdx.x;
    const int s  = (bi < NLONG) ? 39 * bi : 39 * NLONG + 38 * (bi - NLONG);
    const int e  = s + ((bi < NLONG) ? 39 : 38);

    const uint32_t abuf[2] = { sb + SM_A0, sb + SM_A1 };
    const uint32_t bbuf[2] = { sb + SM_B0, sb + SM_B1 };

    auto issue = [&](int g, int p) {
        int m = g / NCHUNK;
        int k = g - m * NCHUNK;
        int gr = m * 128 + lr;
        int f  = gr >> 6;
        int c  = gr & 63;
        int bb = f / T_;
        int tt = f - bb * T_;
        const float* as = x + ((size_t)((bb * C_ + c) * T_ + tt)) * S_ + k * KC + lh * 32;
#pragma unroll
        for (int jj = 0; jj < 8; jj++)
            cp16(abuf[p] + aoff(lr, lh * 8 + jj), as + jj * 4);
        const uint8_t* bs = g_wsq + (size_t)lb * S_ + k * KC + hb * 32;
#pragma unroll
        for (int j = 0; j < 2; j++)
            cp16(bbuf[p] + tswz(lb, hb * 2 + j), bs + j * 16);
    };

    float acc[2][8][4];
#pragma unroll
    for (int mt = 0; mt < 2; mt++)
#pragma unroll
        for (int j = 0; j < 8; j++)
#pragma unroll
            for (int q = 0; q < 4; q++) acc[mt][j][q] = 0.0f;

    issue(s, 0);     CP_COMMIT();
    issue(s + 1, 1); CP_COMMIT();

    float* Tsm = (float*)(smem + SM_T1);

    for (int g = s; g < e; g++) {
        const int p = (g - s) & 1;
        CP_WAIT1();
        __syncthreads();

        const uint32_t Ab = abuf[p], Bb = bbuf[p];
#pragma unroll
        for (int q = 0; q < 2; q++) {
            uint32_t afr[2][4];
#pragma unroll
            for (int mt = 0; mt < 2; mt++) {
                int r0 = wm * 32 + mt * 16 + lrow;
                float4 v;
                asm volatile("ld.shared.v4.f32 {%0,%1,%2,%3}, [%4];"
                    : "=f"(v.x), "=f"(v.y), "=f"(v.z), "=f"(v.w)
                    : "r"(Ab + aoff(r0, q * 8 + lq)));
                afr[mt][0] = pack_e4m3x4(v.x, v.y, v.z, v.w);
                asm volatile("ld.shared.v4.f32 {%0,%1,%2,%3}, [%4];"
                    : "=f"(v.x), "=f"(v.y), "=f"(v.z), "=f"(v.w)
                    : "r"(Ab + aoff(r0 + 8, q * 8 + lq)));
                afr[mt][1] = pack_e4m3x4(v.x, v.y, v.z, v.w);
                asm volatile("ld.shared.v4.f32 {%0,%1,%2,%3}, [%4];"
                    : "=f"(v.x), "=f"(v.y), "=f"(v.z), "=f"(v.w)
                    : "r"(Ab + aoff(r0, q * 8 + 4 + lq)));
                afr[mt][2] = pack_e4m3x4(v.x, v.y, v.z, v.w);
                asm volatile("ld.shared.v4.f32 {%0,%1,%2,%3}, [%4];"
                    : "=f"(v.x), "=f"(v.y), "=f"(v.z), "=f"(v.w)
                    : "r"(Ab + aoff(r0 + 8, q * 8 + 4 + lq)));
                afr[mt][3] = pack_e4m3x4(v.x, v.y, v.z, v.w);
            }
            uint32_t bfr[8][2];
#pragma unroll
            for (int j = 0; j < 8; j++) {
                int n = wn * 64 + j * 8 + lrow;
                asm volatile("ld.shared.b32 %0, [%1];" : "=r"(bfr[j][0])
                             : "r"(Bb + tswz(n, q * 2)     + lq * 4));
                asm volatile("ld.shared.b32 %0, [%1];" : "=r"(bfr[j][1])
                             : "r"(Bb + tswz(n, q * 2 + 1) + lq * 4));
            }
#pragma unroll
            for (int mt = 0; mt < 2; mt++)
#pragma unroll
                for (int j = 0; j < 8; j++)
                    mma_fp8(acc[mt][j], afr[mt], bfr[j]);
        }
        __syncthreads();
        if (g + 2 < e) issue(g + 2, p);
        CP_COMMIT();

        // ---- tile boundary or range end: flush partial R ----
        if ((g + 1 == e) || ((g + 1) % NCHUNK == 0)) {
            int m = g / NCHUNK;
            __syncthreads();
#pragma unroll
            for (int mt = 0; mt < 2; mt++) {
#pragma unroll
                for (int j = 0; j < 8; j++) {
                    int r0  = wm * 32 + mt * 16 + lrow;
                    int col = wn * 64 + j * 8 + lq * 2;
                    uint32_t a0 = sb + SM_T1 + (uint32_t)((r0 * T1_STRIDE + col) * 4);
                    uint32_t a1 = sb + SM_T1 + (uint32_t)(((r0 + 8) * T1_STRIDE + col) * 4);
                    asm volatile("st.shared.v2.f32 [%0], {%1,%2};"
                                 :: "r"(a0), "f"(acc[mt][j][0]), "f"(acc[mt][j][1]));
                    asm volatile("st.shared.v2.f32 [%0], {%1,%2};"
                                 :: "r"(a1), "f"(acc[mt][j][2]), "f"(acc[mt][j][3]));
                }
            }
            __syncthreads();
            {
                int fl = tid >> 7;
                int n  = tid & 127;
                float sum = 0.0f;
#pragma unroll 16
                for (int c2 = 0; c2 < 64; c2++)
                    sum += Tsm[(fl * 64 + c2) * T1_STRIDE + n] * __ldg(&wc[c2 * N_ + n]);
                sum *= g_wsDesc[n];
                int ord = (s > m * NCHUNK) ? 1 : 0;
                g_Rpart[m * 512 + ord * 256 + fl * 128 + n] = sum;
            }
#pragma unroll
            for (int mt = 0; mt < 2; mt++)
#pragma unroll
                for (int j = 0; j < 8; j++)
#pragma unroll
                    for (int q = 0; q < 4; q++) acc[mt][j][q] = 0.0f;
        }
    }
}

// ---------------------------------------------------------------------------
// 3) temporal conv: one warp per (b, n) row
// ---------------------------------------------------------------------------
__global__ void conv_kernel(const float* __restrict__ wt, const float* __restrict__ wb,
                            float* __restrict__ out) {
    __shared__ float rr[8][80];
    __shared__ float wts[8][10];
    int wid = threadIdx.x >> 5, lane = threadIdx.x & 31;
    int row = blockIdx.x * 8 + wid;        // row = b*N + n
    int b = row >> 7, n = row & 127;
    if (lane < 10) wts[wid][lane] = wt[lane * N_ + n];
#pragma unroll
    for (int t0 = lane; t0 < T_; t0 += 32) {
        int f = b * T_ + t0;
        int m = f >> 1, fl = f & 1;
        rr[wid][t0] = g_Rpart[m * 512 + fl * 128 + n]
                    + g_Rpart[m * 512 + 256 + fl * 128 + n];
    }
    __syncwarp();
    float bias = wb[n];
    for (int t0 = lane; t0 < TOUT_; t0 += 32) {
        float sum = bias;
#pragma unroll
        for (int k = 0; k < NT_; k++) sum += rr[wid][t0 + k] * wts[wid][k];
        out[(size_t)row * TOUT_ + t0] = sum;
    }
}

// ---------------------------------------------------------------------------
extern "C" void kernel_launch(void* const* d_in, const int* in_sizes, int n_in,
                              void* d_out, int out_size) {
    (void)in_sizes; (void)n_in; (void)out_size;
    const float* x   = (const float*)d_in[0];
    const float* wc  = (const float*)d_in[2];
    const float* wx  = (const float*)d_in[3];
    const float* wy  = (const float*)d_in[4];
    const float* wsx = (const float*)d_in[5];
    const float* wsy = (const float*)d_in[6];
    const float* wt  = (const float*)d_in[7];
    const float* wb  = (const float*)d_in[8];
    float* out = (float*)d_out;

    cudaFuncSetAttribute(gemm_kernel, cudaFuncAttributeMaxDynamicSharedMemorySize, SMEM_SZ);

    prep_kernel<<<160, 256>>>(wx, wy, wsx, wsy);
    gemm_kernel<<<GRID_G, 256, SMEM_SZ>>>(x, wc);
    conv_kernel<<<(B_ * N_) / 8, 256>>>(wt, wb, out);
}